// round 13
// baseline (speedup 1.0000x reference)
#include <cuda_runtime.h>
#include <cuda_fp16.h>
#include <cstdint>

// Masked LeNet-C3 conv via fp16 mma.sync.m16n8k16 fed by ldmatrix, on sm_103.
// x: [64,6,512,512] f32, W: [16,6,5,5] f32, b: [16] f32 -> out: [64,16,508,508] f32
//
// SMEM input tile is pixel-major: 16B per pixel = [ic0..ic5,0,0] fp16. An A row
// (fixed pixel, k=ic) is one aligned 16B ldmatrix row. K=16 = two taps (2 ics blocks);
// lanes 16-31 address the second tap. 13 K-steps cover the 25 taps.

#define NIC 6
#define NOC 16
#define IH 512
#define IW 512
#define OH 508
#define OW 508
#define TILE_W 64
#define TILE_H 8
#define IN_ROWS 12
#define COLS 68                 // pixel columns 0..67 (64 + 4 halo)
#define NSTEP 13
#define NTHREADS 256

typedef unsigned long long ull;

__host__ __device__ constexpr float conn(int ic, int oc) {
    constexpr int M[NIC][NOC] = {
        {1,0,0,0,1,1,1,0,0,1,1,1,1,0,1,1},
        {1,1,0,0,0,1,1,1,0,0,1,1,1,1,0,1},
        {1,1,1,0,0,0,1,1,1,0,0,1,0,1,1,1},
        {0,1,1,1,0,0,1,1,1,1,0,0,1,0,1,1},
        {0,0,1,1,1,0,0,1,1,1,1,0,1,1,0,1},
        {0,0,0,1,1,1,0,0,1,1,1,1,0,1,1,1},
    };
    return (float)M[ic][oc];
}

__device__ __forceinline__ uint32_t pack_f16x2(float lo, float hi) {
    uint32_t r;
    asm("cvt.rn.f16x2.f32 %0, %1, %2;" : "=r"(r) : "f"(hi), "f"(lo));
    return r;
}

__device__ __forceinline__ uint32_t smem_u32(const void* p) {
    uint32_t a;
    asm("{ .reg .u64 t; cvta.to.shared.u64 t, %1; cvt.u32.u64 %0, t; }" : "=r"(a) : "l"(p));
    return a;
}

// fp16 m16n8k16, f32 accumulate — scalar operands.
#define MMA_F16(d0, d1, d2, d3, a0, a1, a2, a3, b0, b1) \
    asm("mma.sync.aligned.m16n8k16.row.col.f32.f16.f16.f32 " \
        "{%0,%1,%2,%3}, {%4,%5,%6,%7}, {%8,%9}, {%0,%1,%2,%3};" \
        : "+f"(d0), "+f"(d1), "+f"(d2), "+f"(d3) \
        : "r"(a0), "r"(a1), "r"(a2), "r"(a3), "r"(b0), "r"(b1))

__global__ __launch_bounds__(NTHREADS)
void conv_c3_ldsm(const float* __restrict__ x,
                  const float* __restrict__ W,
                  const float* __restrict__ b,
                  float* __restrict__ out)
{
    __shared__ __align__(16) uint4 s_in[IN_ROWS * COLS];   // 13056 B: [row*68+col] = 8 fp16 ics
    __shared__ __align__(16) ull   s_B[NSTEP * 64];        //  6656 B
    __shared__ float s_b[NOC];

    const int tid  = threadIdx.x;
    const int lane = tid & 31;
    const int warp = tid >> 5;
    const int n    = blockIdx.z;
    const int by0  = blockIdx.y * TILE_H;
    const int bx0  = blockIdx.x * TILE_W;

    // ---- Input tile: per pixel gather 6 ics, one STS.128 ----
    const float* xin = x + (size_t)n * NIC * IH * IW;
    #pragma unroll 1
    for (int idx = tid; idx < IN_ROWS * COLS; idx += NTHREADS) {
        int row = idx / COLS;
        int col = idx % COLS;
        int gy  = by0 + row;
        int gx  = bx0 + col;
        float v0=0.f,v1=0.f,v2=0.f,v3=0.f,v4=0.f,v5=0.f;
        if (gy < IH && gx < IW) {
            const float* p = xin + (size_t)gy * IW + gx;
            const size_t PL = (size_t)IH * IW;
            v0 = __ldg(p);        v1 = __ldg(p + PL);     v2 = __ldg(p + 2 * PL);
            v3 = __ldg(p + 3*PL); v4 = __ldg(p + 4 * PL); v5 = __ldg(p + 5 * PL);
        }
        uint4 q;
        q.x = pack_f16x2(v0, v1);
        q.y = pack_f16x2(v2, v3);
        q.z = pack_f16x2(v4, v5);
        q.w = 0u;
        s_in[idx] = q;
    }

    // ---- B table: u64 at [s*64 + nt*32 + g*4 + c4]:
    //   lo = f16x2( w(ic=2c4, tapA, oc), w(ic=2c4+1, tapA, oc) )
    //   hi = same for tapB; oc = nt*8 + g; tapA=2s, tapB=2s+1 (>=25 -> zero)
    #pragma unroll 1
    for (int idx = tid; idx < NSTEP * 64; idx += NTHREADS) {
        int c4 = idx & 3;
        int g  = (idx >> 2) & 7;
        int nt = (idx >> 5) & 1;
        int s  = idx >> 6;
        int oc = nt * 8 + g;
        int tA = 2 * s, tB = 2 * s + 1;
        int ic0 = 2 * c4, ic1 = 2 * c4 + 1;
        float wA0 = (ic0 < NIC && tA < 25) ? W[oc * 150 + ic0 * 25 + tA] * conn(ic0, oc) : 0.f;
        float wA1 = (ic1 < NIC && tA < 25) ? W[oc * 150 + ic1 * 25 + tA] * conn(ic1, oc) : 0.f;
        float wB0 = (ic0 < NIC && tB < 25) ? W[oc * 150 + ic0 * 25 + tB] * conn(ic0, oc) : 0.f;
        float wB1 = (ic1 < NIC && tB < 25) ? W[oc * 150 + ic1 * 25 + tB] * conn(ic1, oc) : 0.f;
        ull lo = (ull)pack_f16x2(wA0, wA1);
        ull hi = (ull)pack_f16x2(wB0, wB1);
        s_B[idx] = lo | (hi << 32);
    }
    if (tid < NOC) s_b[tid] = b[tid];
    __syncthreads();

    // ---- Main loop ----
    const int g  = lane >> 2;
    const int c4 = lane & 3;
    const int wy = warp;

    const uint32_t in_base = smem_u32(s_in);
    const uint32_t b_base  = smem_u32(s_B);
    const int m_local   = lane & 15;               // A row within 16
    const int mloc_off  = m_local * 16;            // bytes
    const bool tap_b    = (lane >= 16);
    const uint32_t bofs0 = b_base + (g * 4 + c4) * 8;        // nt=0
    const uint32_t bofs1 = bofs0 + 32 * 8;                    // nt=1

#define DECL_ACC(mt) \
    float ac##mt##_0_0 = 0.f, ac##mt##_0_1 = 0.f, ac##mt##_0_2 = 0.f, ac##mt##_0_3 = 0.f, \
          ac##mt##_1_0 = 0.f, ac##mt##_1_1 = 0.f, ac##mt##_1_2 = 0.f, ac##mt##_1_3 = 0.f;
    DECL_ACC(0) DECL_ACC(1) DECL_ACC(2) DECL_ACC(3)

#define DO_MT(mt) { \
    uint32_t A0, A1, A2, A3; \
    uint32_t ad = rb + mloc_off + (mt * 16 * 16); \
    asm volatile("ldmatrix.sync.aligned.m8n8.x4.shared.b16 {%0,%1,%2,%3}, [%4];" \
                 : "=r"(A0), "=r"(A1), "=r"(A2), "=r"(A3) : "r"(ad)); \
    MMA_F16(ac##mt##_0_0, ac##mt##_0_1, ac##mt##_0_2, ac##mt##_0_3, \
            A0, A1, A2, A3, bL0, bL1); \
    MMA_F16(ac##mt##_1_0, ac##mt##_1_1, ac##mt##_1_2, ac##mt##_1_3, \
            A0, A1, A2, A3, bH0, bH1); }

    #pragma unroll
    for (int s = 0; s < NSTEP; s++) {
        const int tA = 2 * s;
        const int tBadr = (2 * s + 1 <= 24) ? (2 * s + 1) : 24;   // valid address; weights zero
        const int kyA = tA / 5, kxA = tA % 5;
        const int kyB = tBadr / 5, kxB = tBadr % 5;
        const uint32_t rbA = in_base + (((wy + kyA) * COLS + kxA) * 16);
        const uint32_t rbB = in_base + (((wy + kyB) * COLS + kxB) * 16);
        const uint32_t rb  = tap_b ? rbB : rbA;

        uint32_t bL0, bL1, bH0, bH1;
        asm volatile("ld.shared.v2.u32 {%0,%1}, [%2];"
                     : "=r"(bL0), "=r"(bL1) : "r"(bofs0 + s * 64 * 8));
        asm volatile("ld.shared.v2.u32 {%0,%1}, [%2];"
                     : "=r"(bH0), "=r"(bH1) : "r"(bofs1 + s * 64 * 8));

        DO_MT(0) DO_MT(1) DO_MT(2) DO_MT(3)
    }

    // ---- Epilogue: c0=D[g][2c4], c1=D[g][2c4+1], c2=D[g+8][2c4], c3=D[g+8][2c4+1] ----
    const int y = by0 + wy;
    if (y < OH) {
#define STORE_MT(mt, h) { \
        int oc0 = h * 8 + 2 * c4; \
        float bo0 = s_b[oc0], bo1 = s_b[oc0 + 1]; \
        int x0 = bx0 + mt * 16 + g; \
        size_t base0 = (((size_t)n * NOC + oc0) * OH + y) * OW; \
        size_t base1 = base0 + (size_t)OH * OW; \
        if (x0 < OW) { \
            out[base0 + x0] = ac##mt##_##h##_0 + bo0; \
            out[base1 + x0] = ac##mt##_##h##_1 + bo1; \
        } \
        if (x0 + 8 < OW) { \
            out[base0 + x0 + 8] = ac##mt##_##h##_2 + bo0; \
            out[base1 + x0 + 8] = ac##mt##_##h##_3 + bo1; \
        } }
        STORE_MT(0, 0) STORE_MT(0, 1)
        STORE_MT(1, 0) STORE_MT(1, 1)
        STORE_MT(2, 0) STORE_MT(2, 1)
        STORE_MT(3, 0) STORE_MT(3, 1)
    }
}

extern "C" void kernel_launch(void* const* d_in, const int* in_sizes, int n_in,
                              void* d_out, int out_size) {
    const float* x = (const float*)d_in[0];
    const float* W = (const float*)d_in[1];
    const float* b = (const float*)d_in[2];
    float* out = (float*)d_out;

    const int n_batch = in_sizes[0] / (NIC * IH * IW);   // 64
    dim3 grid((OW + TILE_W - 1) / TILE_W,    // 8
              (OH + TILE_H - 1) / TILE_H,    // 64
              n_batch);                       // 64
    conv_c3_ldsm<<<grid, NTHREADS>>>(x, W, b, out);
}

// round 14
// speedup vs baseline: 1.2230x; 1.2230x over previous
#include <cuda_runtime.h>
#include <cstdint>

// Masked LeNet-C3 conv via TF32 mma.sync.m16n8k8 implicit GEMM, K = input channels.
// x: [64,6,512,512] f32, W: [16,6,5,5] f32, b: [16] f32 -> out: [64,16,508,508] f32
//
// Round 14: K-dimension = ic (8 slots: 6 real + 2 zero pads), one K-step per tap (25).
// SMEM pixel block = 32B: [ic0,ic4,ic1,ic5,ic2,0,ic3,0] f32(tf32-rounded) so each
// thread's A-pair (k=c4, k=c4+4) is one aligned LDS.64. Fully unrolled taps give
// immediate-offset LDS and near-zero address ALU. fp16 k16 path abandoned (L2 pathology).

#define NIC 6
#define NOC 16
#define IH 512
#define IW 512
#define OH 508
#define OW 508
#define TILE_W 64
#define TILE_H 8
#define IN_ROWS 12
#define COLS 68                 // pixel columns 0..67 (64 + 4 halo)
#define PIX_B 32                // bytes per pixel block
#define NTHREADS 256

typedef unsigned long long ull;

__host__ __device__ constexpr float conn(int ic, int oc) {
    constexpr int M[NIC][NOC] = {
        {1,0,0,0,1,1,1,0,0,1,1,1,1,0,1,1},
        {1,1,0,0,0,1,1,1,0,0,1,1,1,1,0,1},
        {1,1,1,0,0,0,1,1,1,0,0,1,0,1,1,1},
        {0,1,1,1,0,0,1,1,1,1,0,0,1,0,1,1},
        {0,0,1,1,1,0,0,1,1,1,1,0,1,1,0,1},
        {0,0,0,1,1,1,0,0,1,1,1,1,0,1,1,1},
    };
    return (float)M[ic][oc];
}

// round-to-nearest-even f32 -> tf32 bit pattern
__device__ __forceinline__ uint32_t f32_to_tf32(float f) {
    uint32_t u = __float_as_uint(f);
    uint32_t r = u + 0xFFFu + ((u >> 13) & 1u);
    return r & 0xFFFFE000u;
}

#define MMA_TF32(d0, d1, d2, d3, a0, a1, a2, a3, b0, b1) \
    asm("mma.sync.aligned.m16n8k8.row.col.f32.tf32.tf32.f32 " \
        "{%0,%1,%2,%3}, {%4,%5,%6,%7}, {%8,%9}, {%0,%1,%2,%3};" \
        : "+f"(d0), "+f"(d1), "+f"(d2), "+f"(d3) \
        : "r"(a0), "r"(a1), "r"(a2), "r"(a3), "r"(b0), "r"(b1))

__global__ __launch_bounds__(NTHREADS, 3)
void conv_c3_tf32ic(const float* __restrict__ x,
                    const float* __restrict__ W,
                    const float* __restrict__ b,
                    float* __restrict__ out)
{
    __shared__ __align__(16) uint32_t s_in[IN_ROWS * COLS * 8];  // 26112 B
    __shared__ __align__(16) ull      s_B[25 * 2 * 8 * 4];       // 12800 B
    __shared__ float s_b[NOC];

    const int tid  = threadIdx.x;
    const int lane = tid & 31;
    const int warp = tid >> 5;
    const int n    = blockIdx.z;
    const int by0  = blockIdx.y * TILE_H;
    const int bx0  = blockIdx.x * TILE_W;

    // ---- Input tile: per pixel gather 6 ics -> 32B interleaved block ----
    // slots: [ic0, ic4, ic1, ic5, ic2, 0, ic3, 0]
    const float* xin = x + (size_t)n * NIC * IH * IW;
    #pragma unroll 1
    for (int idx = tid; idx < IN_ROWS * COLS; idx += NTHREADS) {
        int row = idx / COLS;
        int col = idx % COLS;
        int gy  = by0 + row;
        int gx  = bx0 + col;
        float v0=0.f,v1=0.f,v2=0.f,v3=0.f,v4=0.f,v5=0.f;
        if (gy < IH && gx < IW) {
            const float* p = xin + (size_t)gy * IW + gx;
            const size_t PL = (size_t)IH * IW;
            v0 = __ldg(p);          v1 = __ldg(p + PL);      v2 = __ldg(p + 2 * PL);
            v3 = __ldg(p + 3 * PL); v4 = __ldg(p + 4 * PL);  v5 = __ldg(p + 5 * PL);
        }
        uint32_t* q = s_in + idx * 8;
        uint4 qa, qb;
        qa.x = f32_to_tf32(v0); qa.y = f32_to_tf32(v4);
        qa.z = f32_to_tf32(v1); qa.w = f32_to_tf32(v5);
        qb.x = f32_to_tf32(v2); qb.y = 0u;
        qb.z = f32_to_tf32(v3); qb.w = 0u;
        *(uint4*)(q)     = qa;
        *(uint4*)(q + 4) = qb;
    }

    // ---- B table: ull at [tap*64 + nt*32 + g*4 + c4] (byte off tap*512+nt*256+g*32+c4*8)
    //   lo = tf32 w(ic=c4,  tap, oc=nt*8+g), hi = tf32 w(ic=c4+4, tap, oc)  (ic>=6 -> 0)
    #pragma unroll 1
    for (int idx = tid; idx < 25 * 2 * 8 * 4; idx += NTHREADS) {
        int c4  = idx & 3;
        int g   = (idx >> 2) & 7;
        int nt  = (idx >> 5) & 1;
        int tap = idx >> 6;
        int oc  = nt * 8 + g;
        int ic1 = c4 + 4;
        float w0 = W[oc * 150 + c4 * 25 + tap] * conn(c4, oc);
        float w1 = (ic1 < NIC) ? W[oc * 150 + ic1 * 25 + tap] * conn(ic1, oc) : 0.f;
        s_B[idx] = (ull)f32_to_tf32(w0) | ((ull)f32_to_tf32(w1) << 32);
    }
    if (tid < NOC) s_b[tid] = b[tid];
    __syncthreads();

    // ---- Main loop: 25 taps, fully unrolled, immediate-offset LDS ----
    const int g  = lane >> 2;
    const int c4 = lane & 3;
    const int wy = warp;

    const char* abase = (const char*)s_in + ((size_t)(wy * COLS + g)) * PIX_B + c4 * 8;
    const char* bbase = (const char*)s_B  + g * 32 + c4 * 8;

#define DECL_ACC(mt) \
    float ac##mt##_0_0 = 0.f, ac##mt##_0_1 = 0.f, ac##mt##_0_2 = 0.f, ac##mt##_0_3 = 0.f, \
          ac##mt##_1_0 = 0.f, ac##mt##_1_1 = 0.f, ac##mt##_1_2 = 0.f, ac##mt##_1_3 = 0.f;
    DECL_ACC(0) DECL_ACC(1) DECL_ACC(2) DECL_ACC(3)

    // A pair loads: (a0,a2) at pixel g, (a1,a3) at pixel g+8 (+8*32=256B)
#define DO_MT(mt) { \
    uint2 w02 = *(const uint2*)(ap + (mt) * (16 * PIX_B)); \
    uint2 w13 = *(const uint2*)(ap + (mt) * (16 * PIX_B) + 8 * PIX_B); \
    MMA_TF32(ac##mt##_0_0, ac##mt##_0_1, ac##mt##_0_2, ac##mt##_0_3, \
             w02.x, w13.x, w02.y, w13.y, bL0, bL1); \
    MMA_TF32(ac##mt##_1_0, ac##mt##_1_1, ac##mt##_1_2, ac##mt##_1_3, \
             w02.x, w13.x, w02.y, w13.y, bH0, bH1); }

    #pragma unroll
    for (int tap = 0; tap < 25; tap++) {
        const int ky = tap / 5;
        const int kx = tap % 5;
        const char* ap = abase + (ky * COLS + kx) * PIX_B;
        uint2 bl = *(const uint2*)(bbase + tap * 512);
        uint2 bh = *(const uint2*)(bbase + tap * 512 + 256);
        uint32_t bL0 = bl.x, bL1 = bl.y;
        uint32_t bH0 = bh.x, bH1 = bh.y;
        DO_MT(0) DO_MT(1) DO_MT(2) DO_MT(3)
    }

    // ---- Epilogue: c0=D[g][2c4], c1=D[g][2c4+1], c2=D[g+8][2c4], c3=D[g+8][2c4+1] ----
    const int y = by0 + wy;
    if (y < OH) {
#define STORE_MT(mt, h) { \
        int oc0 = h * 8 + 2 * c4; \
        float bo0 = s_b[oc0], bo1 = s_b[oc0 + 1]; \
        int x0 = bx0 + mt * 16 + g; \
        size_t base0 = (((size_t)n * NOC + oc0) * OH + y) * OW; \
        size_t base1 = base0 + (size_t)OH * OW; \
        if (x0 < OW) { \
            out[base0 + x0] = ac##mt##_##h##_0 + bo0; \
            out[base1 + x0] = ac##mt##_##h##_1 + bo1; \
        } \
        if (x0 + 8 < OW) { \
            out[base0 + x0 + 8] = ac##mt##_##h##_2 + bo0; \
            out[base1 + x0 + 8] = ac##mt##_##h##_3 + bo1; \
        } }
        STORE_MT(0, 0) STORE_MT(0, 1)
        STORE_MT(1, 0) STORE_MT(1, 1)
        STORE_MT(2, 0) STORE_MT(2, 1)
        STORE_MT(3, 0) STORE_MT(3, 1)
    }
}

extern "C" void kernel_launch(void* const* d_in, const int* in_sizes, int n_in,
                              void* d_out, int out_size) {
    const float* x = (const float*)d_in[0];
    const float* W = (const float*)d_in[1];
    const float* b = (const float*)d_in[2];
    float* out = (float*)d_out;

    const int n_batch = in_sizes[0] / (NIC * IH * IW);   // 64
    dim3 grid((OW + TILE_W - 1) / TILE_W,    // 8
              (OH + TILE_H - 1) / TILE_H,    // 64
              n_batch);                       // 64
    conv_c3_tf32ic<<<grid, NTHREADS>>>(x, W, b, out);
}

// round 15
// speedup vs baseline: 3.5309x; 2.8870x over previous
#include <cuda_runtime.h>
#include <cstdint>

// Masked LeNet-C3 conv via TF32 mma.sync.m16n8k8 implicit GEMM on sm_103.
// x: [64,6,512,512] f32, W: [16,6,5,5] f32, b: [16] f32 -> out: [64,16,508,508] f32
//
// Round 15 = Round 12's proven-clean compute loop (1755us, L2=11%) with the
// prologue/epilogue overhead stripped: warp-per-row loader (no div/mod per element),
// single-instruction cvt.rna.tf32.f32, shift-only B indexing, hoisted store bases.

#define NIC 6
#define NOC 16
#define IH 512
#define IW 512
#define OH 508
#define OW 508
#define TILE_W 64
#define TILE_H 8
#define IN_ROWS 12
#define IN_W 72             // 64 + 4 halo + 4 zero pad (A reads reach col 70)
#define NTHREADS 256

__host__ __device__ constexpr float conn(int ic, int oc) {
    constexpr int M[NIC][NOC] = {
        {1,0,0,0,1,1,1,0,0,1,1,1,1,0,1,1},
        {1,1,0,0,0,1,1,1,0,0,1,1,1,1,0,1},
        {1,1,1,0,0,0,1,1,1,0,0,1,0,1,1,1},
        {0,1,1,1,0,0,1,1,1,1,0,0,1,0,1,1},
        {0,0,1,1,1,0,0,1,1,1,1,0,1,1,0,1},
        {0,0,0,1,1,1,0,0,1,1,1,1,0,1,1,1},
    };
    return (float)M[ic][oc];
}

// single-instruction round-to-nearest-even f32 -> tf32 (sm_80+ base target)
__device__ __forceinline__ uint32_t cvt_tf32(float f) {
    uint32_t r;
    asm("cvt.rna.tf32.f32 %0, %1;" : "=r"(r) : "f"(f));
    return r;
}

#define MMA_TF32(d0, d1, d2, d3, a0, a1, a2, a3, b0, b1) \
    asm("mma.sync.aligned.m16n8k8.row.col.f32.tf32.tf32.f32 " \
        "{%0,%1,%2,%3}, {%4,%5,%6,%7}, {%8,%9}, {%0,%1,%2,%3};" \
        : "+f"(d0), "+f"(d1), "+f"(d2), "+f"(d3) \
        : "r"(a0), "r"(a1), "r"(a2), "r"(a3), "r"(b0), "r"(b1))

__global__ __launch_bounds__(NTHREADS, 3)
void conv_c3_mma(const float* __restrict__ x,
                 const float* __restrict__ W,
                 const float* __restrict__ b,
                 float* __restrict__ out)
{
    __shared__ float    s_in[NIC][IN_ROWS][IN_W];        // 20736 B (tf32-rounded)
    __shared__ uint32_t s_B[NIC * 5 * NOC * 8];          // 15360 B
    __shared__ float    s_b[NOC];

    const int tid  = threadIdx.x;
    const int lane = tid & 31;
    const int warp = tid >> 5;
    const int n    = blockIdx.z;
    const int by0  = blockIdx.y * TILE_H;
    const int bx0  = blockIdx.x * TILE_W;

    // ---- Input tile loader: one warp per (ic,row); no per-element div/mod ----
    const float* xin = x + (size_t)n * NIC * IH * IW;
    #pragma unroll 1
    for (int rowi = warp; rowi < NIC * IN_ROWS; rowi += NTHREADS / 32) {
        int ic = rowi / IN_ROWS;        // const-div by 12 -> mul/shift
        int r  = rowi - ic * IN_ROWS;
        int gy = by0 + r;
        const float* src = xin + ((size_t)ic * IH + gy) * IW + bx0;
        float* dst = &s_in[ic][r][0];
        #pragma unroll
        for (int cc = 0; cc < 3; cc++) {
            int c = lane + cc * 32;
            if (c < IN_W) {
                float v = 0.0f;
                if (c < TILE_W + 4 && gy < IH && bx0 + c < IW) v = __ldg(src + c);
                dst[c] = __uint_as_float(cvt_tf32(v));
            }
        }
    }

    // ---- Masked weight table: s_B[((ic*5+ky)*16 + oc)*8 + kx], kx>=5 -> 0 ----
    #pragma unroll 1
    for (int idx = tid; idx < NIC * 5 * NOC * 8; idx += NTHREADS) {
        int kx   = idx & 7;
        int oc   = (idx >> 3) & 15;
        int rest = idx >> 7;            // 0..29 = ic*5 + ky
        int ic   = rest / 5;
        int ky   = rest - ic * 5;
        float wv = 0.0f;
        if (kx < 5) wv = W[oc * (NIC * 25) + ic * 25 + ky * 5 + kx] * conn(ic, oc);
        s_B[idx] = cvt_tf32(wv);
    }
    if (tid < NOC) s_b[tid] = b[tid];
    __syncthreads();

    // ---- Main loop: 30 K-steps (ic,ky), 8 HMMA each (identical to round 12) ----
    const int g    = lane >> 2;
    const int c4   = lane & 3;
    const int aoff = g + c4;
    const int boff = g * 8 + c4;
    const int wy   = warp;

#define DECL_ACC(mt) \
    float ac##mt##_0_0 = 0.f, ac##mt##_0_1 = 0.f, ac##mt##_0_2 = 0.f, ac##mt##_0_3 = 0.f, \
          ac##mt##_1_0 = 0.f, ac##mt##_1_1 = 0.f, ac##mt##_1_2 = 0.f, ac##mt##_1_3 = 0.f;
    DECL_ACC(0) DECL_ACC(1) DECL_ACC(2) DECL_ACC(3)

#define DO_MT(mt) { \
    uint32_t A0 = __float_as_uint(rp[mt * 16 + 0]); \
    uint32_t A1 = __float_as_uint(rp[mt * 16 + 8]); \
    uint32_t A2 = __float_as_uint(rp[mt * 16 + 4]); \
    uint32_t A3 = __float_as_uint(rp[mt * 16 + 12]); \
    MMA_TF32(ac##mt##_0_0, ac##mt##_0_1, ac##mt##_0_2, ac##mt##_0_3, \
             A0, A1, A2, A3, bL0, bL1); \
    MMA_TF32(ac##mt##_1_0, ac##mt##_1_1, ac##mt##_1_2, ac##mt##_1_3, \
             A0, A1, A2, A3, bH0, bH1); }

    #pragma unroll 1
    for (int ic = 0; ic < NIC; ic++) {
        #pragma unroll
        for (int ky = 0; ky < 5; ky++) {
            const uint32_t* Bp = s_B + (ic * 5 + ky) * (NOC * 8);
            uint32_t bL0 = Bp[boff];
            uint32_t bL1 = Bp[boff + 4];
            uint32_t bH0 = Bp[64 + boff];
            uint32_t bH1 = Bp[64 + boff + 4];
            const float* rp = &s_in[ic][wy + ky][aoff];
            DO_MT(0) DO_MT(1) DO_MT(2) DO_MT(3)
        }
    }

    // ---- Epilogue: hoisted base pointers; c0=D[g][2c4] etc. ----
    const int y = by0 + wy;
    if (y < OH) {
        const int xg = bx0 + g;
        float* orow = out + ((size_t)n * NOC * OH + y) * OW;
#define STORE_MT(mt, h) { \
        int oc0 = h * 8 + 2 * c4; \
        float bo0 = s_b[oc0], bo1 = s_b[oc0 + 1]; \
        float* o0 = orow + (size_t)oc0 * OH * OW; \
        float* o1 = o0 + (size_t)OH * OW; \
        int x0 = xg + mt * 16; \
        if (x0 < OW) { \
            o0[x0] = ac##mt##_##h##_0 + bo0; \
            o1[x0] = ac##mt##_##h##_1 + bo1; \
        } \
        if (x0 + 8 < OW) { \
            o0[x0 + 8] = ac##mt##_##h##_2 + bo0; \
            o1[x0 + 8] = ac##mt##_##h##_3 + bo1; \
        } }
        STORE_MT(0, 0) STORE_MT(0, 1)
        STORE_MT(1, 0) STORE_MT(1, 1)
        STORE_MT(2, 0) STORE_MT(2, 1)
        STORE_MT(3, 0) STORE_MT(3, 1)
    }
}

extern "C" void kernel_launch(void* const* d_in, const int* in_sizes, int n_in,
                              void* d_out, int out_size) {
    const float* x = (const float*)d_in[0];
    const float* W = (const float*)d_in[1];
    const float* b = (const float*)d_in[2];
    float* out = (float*)d_out;

    const int n_batch = in_sizes[0] / (NIC * IH * IW);   // 64
    dim3 grid((OW + TILE_W - 1) / TILE_W,    // 8
              (OH + TILE_H - 1) / TILE_H,    // 64
              n_batch);                       // 64
    conv_c3_mma<<<grid, NTHREADS>>>(x, W, b, out);
}

// round 16
// speedup vs baseline: 3.8722x; 1.0967x over previous
#include <cuda_runtime.h>
#include <cstdint>

// Masked LeNet-C3 conv via TF32 mma.sync.m16n8k8 implicit GEMM on sm_103.
// x: [64,6,512,512] f32, W: [16,6,5,5] f32, b: [16] f32 -> out: [64,16,508,508] f32
//
// Round 16: 2 output rows per warp with ky register-rolling A-buffers:
// row0's fragment at step ky+1 == row1's at step ky, so 5 ky steps need only 6
// row-loads instead of 10, and B fragments are shared by both rows. Main-loop
// LDS drops ~1.7x vs round 15 (proven clean: scalar LDS.32, unroll-1 ic loop).

#define NIC 6
#define NOC 16
#define IH 512
#define IW 512
#define OH 508
#define OW 508
#define TILE_W 64
#define TILE_H 16
#define IN_ROWS 20          // TILE_H + 4
#define IN_W 72             // 64 + 4 halo + 4 zero pad (A reads reach col 70)
#define IC_STRIDE (IN_ROWS * IN_W)
#define NTHREADS 256
#define SMEM_BYTES ((NIC * IC_STRIDE) * 4 + (NIC * 5 * NOC * 8) * 4 + NOC * 4)

__host__ __device__ constexpr float conn(int ic, int oc) {
    constexpr int M[NIC][NOC] = {
        {1,0,0,0,1,1,1,0,0,1,1,1,1,0,1,1},
        {1,1,0,0,0,1,1,1,0,0,1,1,1,1,0,1},
        {1,1,1,0,0,0,1,1,1,0,0,1,0,1,1,1},
        {0,1,1,1,0,0,1,1,1,1,0,0,1,0,1,1},
        {0,0,1,1,1,0,0,1,1,1,1,0,1,1,0,1},
        {0,0,0,1,1,1,0,0,1,1,1,1,0,1,1,1},
    };
    return (float)M[ic][oc];
}

__device__ __forceinline__ uint32_t cvt_tf32(float f) {
    uint32_t r;
    asm("cvt.rna.tf32.f32 %0, %1;" : "=r"(r) : "f"(f));
    return r;
}

#define MMA_TF32(d0, d1, d2, d3, a0, a1, a2, a3, b0, b1) \
    asm("mma.sync.aligned.m16n8k8.row.col.f32.tf32.tf32.f32 " \
        "{%0,%1,%2,%3}, {%4,%5,%6,%7}, {%8,%9}, {%0,%1,%2,%3};" \
        : "+f"(d0), "+f"(d1), "+f"(d2), "+f"(d3) \
        : "r"(a0), "r"(a1), "r"(a2), "r"(a3), "r"(b0), "r"(b1))

__global__ __launch_bounds__(NTHREADS, 2)
void conv_c3_mma(const float* __restrict__ x,
                 const float* __restrict__ W,
                 const float* __restrict__ b,
                 float* __restrict__ out)
{
    extern __shared__ float smem[];
    float*    s_in = smem;                                    // 6*20*72 floats
    uint32_t* s_B  = (uint32_t*)(smem + NIC * IC_STRIDE);     // 6*5*16*8 u32
    float*    s_b  = (float*)(s_B + NIC * 5 * NOC * 8);

    const int tid  = threadIdx.x;
    const int lane = tid & 31;
    const int warp = tid >> 5;
    const int n    = blockIdx.z;
    const int by0  = blockIdx.y * TILE_H;
    const int bx0  = blockIdx.x * TILE_W;

    // ---- Input tile loader: warp per (ic,row), tf32-rounded, zero-padded ----
    const float* xin = x + (size_t)n * NIC * IH * IW;
    #pragma unroll 1
    for (int rowi = warp; rowi < NIC * IN_ROWS; rowi += NTHREADS / 32) {
        int ic = rowi / IN_ROWS;
        int r  = rowi - ic * IN_ROWS;
        int gy = by0 + r;
        const float* src = xin + ((size_t)ic * IH + gy) * IW + bx0;
        float* dst = s_in + (ic * IN_ROWS + r) * IN_W;
        #pragma unroll
        for (int cc = 0; cc < 3; cc++) {
            int c = lane + cc * 32;
            if (c < IN_W) {
                float v = 0.0f;
                if (c < TILE_W + 4 && gy < IH && bx0 + c < IW) v = __ldg(src + c);
                dst[c] = __uint_as_float(cvt_tf32(v));
            }
        }
    }

    // ---- Masked weight table: s_B[((ic*5+ky)*16 + oc)*8 + kx], kx>=5 -> 0 ----
    #pragma unroll 1
    for (int idx = tid; idx < NIC * 5 * NOC * 8; idx += NTHREADS) {
        int kx   = idx & 7;
        int oc   = (idx >> 3) & 15;
        int rest = idx >> 7;
        int ic   = rest / 5;
        int ky   = rest - ic * 5;
        float wv = 0.0f;
        if (kx < 5) wv = W[oc * (NIC * 25) + ic * 25 + ky * 5 + kx] * conn(ic, oc);
        s_B[idx] = cvt_tf32(wv);
    }
    if (tid < NOC) s_b[tid] = b[tid];
    __syncthreads();

    // ---- Main loop: 2 rows/warp, ky-rolled A buffers ----
    const int g    = lane >> 2;
    const int c4   = lane & 3;
    const int aoff = g + c4;
    const int boff = g * 8 + c4;
    const int r0   = 2 * warp;          // first output row of this warp

#define DECL_MT(r, mt) \
    float ar##r##_##mt##_0_0 = 0.f, ar##r##_##mt##_0_1 = 0.f, \
          ar##r##_##mt##_0_2 = 0.f, ar##r##_##mt##_0_3 = 0.f, \
          ar##r##_##mt##_1_0 = 0.f, ar##r##_##mt##_1_1 = 0.f, \
          ar##r##_##mt##_1_2 = 0.f, ar##r##_##mt##_1_3 = 0.f;
    DECL_MT(0,0) DECL_MT(0,1) DECL_MT(0,2) DECL_MT(0,3)
    DECL_MT(1,0) DECL_MT(1,1) DECL_MT(1,2) DECL_MT(1,3)

#define DECL_AB(P) \
    uint32_t P##_0_0, P##_0_1, P##_0_2, P##_0_3, \
             P##_1_0, P##_1_1, P##_1_2, P##_1_3, \
             P##_2_0, P##_2_1, P##_2_2, P##_2_3, \
             P##_3_0, P##_3_1, P##_3_2, P##_3_3;
    DECL_AB(X) DECL_AB(Y)

#define LOAD_A(P, rpp) { \
    P##_0_0 = __float_as_uint((rpp)[0]);  P##_0_1 = __float_as_uint((rpp)[8]); \
    P##_0_2 = __float_as_uint((rpp)[4]);  P##_0_3 = __float_as_uint((rpp)[12]); \
    P##_1_0 = __float_as_uint((rpp)[16]); P##_1_1 = __float_as_uint((rpp)[24]); \
    P##_1_2 = __float_as_uint((rpp)[20]); P##_1_3 = __float_as_uint((rpp)[28]); \
    P##_2_0 = __float_as_uint((rpp)[32]); P##_2_1 = __float_as_uint((rpp)[40]); \
    P##_2_2 = __float_as_uint((rpp)[36]); P##_2_3 = __float_as_uint((rpp)[44]); \
    P##_3_0 = __float_as_uint((rpp)[48]); P##_3_1 = __float_as_uint((rpp)[56]); \
    P##_3_2 = __float_as_uint((rpp)[52]); P##_3_3 = __float_as_uint((rpp)[60]); }

#define LOADB(ky) { \
    const uint32_t* Bq = Bp + (ky) * (NOC * 8); \
    bL0 = Bq[boff];      bL1 = Bq[boff + 4]; \
    bH0 = Bq[64 + boff]; bH1 = Bq[64 + boff + 4]; }

#define MMA_MT_R(r, mt, P) \
    MMA_TF32(ar##r##_##mt##_0_0, ar##r##_##mt##_0_1, ar##r##_##mt##_0_2, ar##r##_##mt##_0_3, \
             P##_##mt##_0, P##_##mt##_1, P##_##mt##_2, P##_##mt##_3, bL0, bL1); \
    MMA_TF32(ar##r##_##mt##_1_0, ar##r##_##mt##_1_1, ar##r##_##mt##_1_2, ar##r##_##mt##_1_3, \
             P##_##mt##_0, P##_##mt##_1, P##_##mt##_2, P##_##mt##_3, bH0, bH1);

#define MMA_ROW(r, P) \
    MMA_MT_R(r, 0, P) MMA_MT_R(r, 1, P) MMA_MT_R(r, 2, P) MMA_MT_R(r, 3, P)

    const float* rpw = s_in + r0 * IN_W + aoff;

    #pragma unroll 1
    for (int ic = 0; ic < NIC; ic++) {
        const float*    rp = rpw + ic * IC_STRIDE;
        const uint32_t* Bp = s_B + ic * 5 * (NOC * 8);
        uint32_t bL0, bL1, bH0, bH1;

        LOAD_A(X, rp)                 // smem row r0
        LOAD_A(Y, rp + IN_W)          // smem row r0+1
        LOADB(0)  MMA_ROW(0, X)  MMA_ROW(1, Y)
        LOAD_A(X, rp + 2 * IN_W)      // smem row r0+2
        LOADB(1)  MMA_ROW(0, Y)  MMA_ROW(1, X)
        LOAD_A(Y, rp + 3 * IN_W)      // smem row r0+3
        LOADB(2)  MMA_ROW(0, X)  MMA_ROW(1, Y)
        LOAD_A(X, rp + 4 * IN_W)      // smem row r0+4
        LOADB(3)  MMA_ROW(0, Y)  MMA_ROW(1, X)
        LOAD_A(Y, rp + 5 * IN_W)      // smem row r0+5
        LOADB(4)  MMA_ROW(0, X)  MMA_ROW(1, Y)
    }

    // ---- Epilogue: per row, c0=D[g][2c4], c1=D[g][2c4+1], c2=D[g+8][..], c3=.. ----
    const int xg = bx0 + g;

#define STORE_MT_R(r, mt, h) { \
    int oc0 = h * 8 + 2 * c4; \
    float bo0 = s_b[oc0], bo1 = s_b[oc0 + 1]; \
    float* o0 = orow + (size_t)oc0 * OH * OW; \
    float* o1 = o0 + (size_t)OH * OW; \
    int x0 = xg + mt * 16; \
    if (x0 < OW) { \
        o0[x0] = ar##r##_##mt##_##h##_0 + bo0; \
        o1[x0] = ar##r##_##mt##_##h##_1 + bo1; \
    } \
    if (x0 + 8 < OW) { \
        o0[x0 + 8] = ar##r##_##mt##_##h##_2 + bo0; \
        o1[x0 + 8] = ar##r##_##mt##_##h##_3 + bo1; \
    } }

    {
        const int y = by0 + r0;
        if (y < OH) {
            float* orow = out + ((size_t)n * NOC * OH + y) * OW;
            STORE_MT_R(0, 0, 0) STORE_MT_R(0, 0, 1)
            STORE_MT_R(0, 1, 0) STORE_MT_R(0, 1, 1)
            STORE_MT_R(0, 2, 0) STORE_MT_R(0, 2, 1)
            STORE_MT_R(0, 3, 0) STORE_MT_R(0, 3, 1)
        }
    }
    {
        const int y = by0 + r0 + 1;
        if (y < OH) {
            float* orow = out + ((size_t)n * NOC * OH + y) * OW;
            STORE_MT_R(1, 0, 0) STORE_MT_R(1, 0, 1)
            STORE_MT_R(1, 1, 0) STORE_MT_R(1, 1, 1)
            STORE_MT_R(1, 2, 0) STORE_MT_R(1, 2, 1)
            STORE_MT_R(1, 3, 0) STORE_MT_R(1, 3, 1)
        }
    }
}

extern "C" void kernel_launch(void* const* d_in, const int* in_sizes, int n_in,
                              void* d_out, int out_size) {
    const float* x = (const float*)d_in[0];
    const float* W = (const float*)d_in[1];
    const float* b = (const float*)d_in[2];
    float* out = (float*)d_out;

    cudaFuncSetAttribute(conv_c3_mma,
                         cudaFuncAttributeMaxDynamicSharedMemorySize, SMEM_BYTES);

    const int n_batch = in_sizes[0] / (NIC * IH * IW);   // 64
    dim3 grid((OW + TILE_W - 1) / TILE_W,    // 8
              (OH + TILE_H - 1) / TILE_H,    // 32
              n_batch);                       // 64
    conv_c3_mma<<<grid, NTHREADS, SMEM_BYTES>>>(x, W, b, out);
}